// round 12
// baseline (speedup 1.0000x reference)
#include <cuda_runtime.h>
#include <cuda_fp16.h>
#include <cstdint>

// DigitCapsules dynamic routing, GB300 sm_103a
// B=256, C=10, I=1152, DI=8, DO=16, 3 routing iterations.
//
// R12 = R11 with the Ws-staging index bug fixed (ii was f>>10, must be
// f/1280 -> OOB W read crashed R11).
// uhat: block = 8 i's (grid 144, one wave), smem-transposed stores
// (coalesced, 4 lines/request vs 32 before) + FFMA2 compute.
// route: R4 version verbatim (51.7us measured).

#define BSZ  256
#define CCL  10
#define ICAP 1152
#define DOV  16
#define DIV  8
#define NT   (ICAP / 32)   // route: 36 tiles of 32 capsules

#define ICH  8             // i's per uhat block
#define ROWB 272           // padded smem row stride (bytes)

// dynamic smem layout for uhat
#define XS_OFF  0
#define BUF_OFF (256 * ROWB)                 // 69632
#define WS_OFF  (2 * 256 * ROWB)             // 139264
#define WS_BYTES (ICH * CCL * DIV * DOV * 4) // 40960
#define UH_SMEM (WS_OFF + WS_BYTES)          // 180224

typedef unsigned long long ull;

__device__ __align__(256) __half g_uhat[(size_t)BSZ * CCL * ICAP * DOV]; // 94.4 MB

// ---------------- packed f32x2 helpers (exact fp32 SIMD-2) ------------------
static __device__ __forceinline__ ull pack2(float x, float y) {
    ull r; asm("mov.b64 %0, {%1, %2};" : "=l"(r) : "f"(x), "f"(y)); return r;
}
static __device__ __forceinline__ void unpack2(ull v, float& x, float& y) {
    asm("mov.b64 {%0, %1}, %2;" : "=f"(x), "=f"(y) : "l"(v));
}
static __device__ __forceinline__ ull fma2(ull a, ull b, ull c) {
    ull d; asm("fma.rn.f32x2 %0, %1, %2, %3;" : "=l"(d) : "l"(a), "l"(b), "l"(c));
    return d;
}
static __device__ __forceinline__ unsigned int pack_h2(float a, float b) {
    __half2 h = __floats2half2_rn(a, b);
    return *reinterpret_cast<unsigned int*>(&h);
}

// ---------------------------------------------------------------------------
// K_uhat v2: grid = I/8 = 144 blocks, 256 threads = b.
// Phase 0: stage x[:, i0:i0+8, :] (68 KB) and W transposed [ii][c][k][d] (40 KB).
// Per c: compute (FFMA2) -> padded smem buf -> coalesced STG.128 flush.
// ---------------------------------------------------------------------------
__global__ __launch_bounds__(256) void uhat_kernel(
    const float* __restrict__ x, const float* __restrict__ W)
{
    extern __shared__ unsigned char sm[];
    const int i0 = blockIdx.x * ICH;
    const int t  = threadIdx.x;

    // stage x: 256 b x 256 B (coalesced: 16 consecutive 16B chunks per b)
    for (int e = t; e < 256 * 16; e += 256) {
        int b = e >> 4, ch = e & 15;
        uint4 v = *reinterpret_cast<const uint4*>(
            x + (size_t)b * (ICAP * DIV) + (size_t)i0 * DIV + ch * 4);
        *reinterpret_cast<uint4*>(sm + XS_OFF + b * ROWB + ch * 16) = v;
    }
    // stage W transposed: Ws[ii][c][k][d]  (1280 entries per ii -- FIXED)
    float* Ws = reinterpret_cast<float*>(sm + WS_OFF);
    for (int f = t; f < ICH * CCL * DOV * DIV; f += 256) {
        int ii  = f / (CCL * DOV * DIV);          // 0..7
        int rem = f - ii * (CCL * DOV * DIV);     // 0..1279
        int c   = rem >> 7;                       // 0..9
        int dk  = rem & 127;                      // d*8 + k (W's native order)
        int d   = dk >> 3, k = dk & 7;
        Ws[((ii * CCL + c) * DIV + k) * DOV + d] =
            W[((size_t)c * ICAP + i0 + ii) * (DOV * DIV) + dk];
    }
    __syncthreads();

    #pragma unroll 1
    for (int c = 0; c < CCL; c++) {
        // ---- compute: thread t = b, its 8 i's for this c
        #pragma unroll
        for (int ii = 0; ii < ICH; ii++) {
            const float4* xp = reinterpret_cast<const float4*>(
                sm + XS_OFF + t * ROWB + ii * 32);
            float4 xa = xp[0], xb = xp[1];
            ull xx[8];
            xx[0] = pack2(xa.x, xa.x); xx[1] = pack2(xa.y, xa.y);
            xx[2] = pack2(xa.z, xa.z); xx[3] = pack2(xa.w, xa.w);
            xx[4] = pack2(xb.x, xb.x); xx[5] = pack2(xb.y, xb.y);
            xx[6] = pack2(xb.z, xb.z); xx[7] = pack2(xb.w, xb.w);

            ull acc[8];
            #pragma unroll
            for (int j = 0; j < 8; j++) acc[j] = 0ULL;

            const float* wb = Ws + ((ii * CCL + c) * DIV) * DOV;
            #pragma unroll
            for (int k = 0; k < DIV; k++) {
                const double2* wk = reinterpret_cast<const double2*>(wb + k * DOV);
                double2 w0 = wk[0], w1 = wk[1], w2 = wk[2], w3 = wk[3];
                acc[0] = fma2(__double_as_longlong(w0.x), xx[k], acc[0]);
                acc[1] = fma2(__double_as_longlong(w0.y), xx[k], acc[1]);
                acc[2] = fma2(__double_as_longlong(w1.x), xx[k], acc[2]);
                acc[3] = fma2(__double_as_longlong(w1.y), xx[k], acc[3]);
                acc[4] = fma2(__double_as_longlong(w2.x), xx[k], acc[4]);
                acc[5] = fma2(__double_as_longlong(w2.y), xx[k], acc[5]);
                acc[6] = fma2(__double_as_longlong(w3.x), xx[k], acc[6]);
                acc[7] = fma2(__double_as_longlong(w3.y), xx[k], acc[7]);
            }

            unsigned int h[8];
            #pragma unroll
            for (int j = 0; j < 8; j++) {
                float lo, hi; unpack2(acc[j], lo, hi);
                h[j] = pack_h2(lo, hi);
            }
            unsigned char* bp = sm + BUF_OFF + t * ROWB + ii * 32;
            *reinterpret_cast<uint4*>(bp)      = make_uint4(h[0], h[1], h[2], h[3]);
            *reinterpret_cast<uint4*>(bp + 16) = make_uint4(h[4], h[5], h[6], h[7]);
        }
        __syncthreads();

        // ---- coalesced flush: consecutive threads -> consecutive 16B chunks
        for (int m = t; m < 256 * 16; m += 256) {
            int b = m >> 4, ch = m & 15;
            uint4 v = *reinterpret_cast<const uint4*>(
                sm + BUF_OFF + b * ROWB + ch * 16);
            *reinterpret_cast<uint4*>(
                reinterpret_cast<unsigned char*>(g_uhat)
                + (((size_t)b * CCL + c) * ICAP + i0) * 32 + ch * 16) = v;
        }
        __syncthreads();
    }
}

// ---------------------------------------------------------------------------
// route_kernel: R4 version VERBATIM (51.7us measured).
// ---------------------------------------------------------------------------
static __device__ __forceinline__ void unpack16(const uint4& a, const uint4& b,
                                                float* __restrict__ u) {
    const __half2* ha = reinterpret_cast<const __half2*>(&a);
    const __half2* hb = reinterpret_cast<const __half2*>(&b);
    #pragma unroll
    for (int q = 0; q < 4; q++) {
        float2 f = __half22float2(ha[q]);
        u[q * 2] = f.x; u[q * 2 + 1] = f.y;
    }
    #pragma unroll
    for (int q = 0; q < 4; q++) {
        float2 f = __half22float2(hb[q]);
        u[8 + q * 2] = f.x; u[8 + q * 2 + 1] = f.y;
    }
}

__global__ __launch_bounds__(320, 2) void route_kernel(float* __restrict__ out)
{
    const int b  = blockIdx.x;
    const int c  = threadIdx.x >> 5;
    const int ii = threadIdx.x & 31;

    __shared__ float e_s[2][CCL][33];

    const __half* ub = g_uhat + ((size_t)b * CCL + c) * (size_t)ICAP * DOV;

    float vr[DOV];
    #pragma unroll
    for (int j = 0; j < DOV; j++) vr[j] = 0.0f;

    float sac[DOV];

    // ---------------- iteration 0: uniform weights 0.1, no barriers
    #pragma unroll
    for (int j = 0; j < DOV; j++) sac[j] = 0.0f;
    {
        const uint4* p0 = reinterpret_cast<const uint4*>(ub + (size_t)ii * DOV);
        uint4 ua = p0[0], ux = p0[1];
        for (int ti = 0; ti < NT; ti++) {
            const int tn = (ti + 1 < NT) ? (ti + 1) : (NT - 1);
            const uint4* pn = reinterpret_cast<const uint4*>(
                ub + (size_t)(tn * 32 + ii) * DOV);
            uint4 na = pn[0], nb = pn[1];

            float u[DOV];
            unpack16(ua, ux, u);
            #pragma unroll
            for (int j = 0; j < DOV; j++) sac[j] = fmaf(0.1f, u[j], sac[j]);

            ua = na; ux = nb;
        }
    }
    #pragma unroll
    for (int off = 16; off > 0; off >>= 1)
        #pragma unroll
        for (int j = 0; j < DOV; j++)
            sac[j] += __shfl_xor_sync(0xffffffffu, sac[j], off);
    {
        float sq = 0.0f;
        #pragma unroll
        for (int j = 0; j < DOV; j++) sq = fmaf(sac[j], sac[j], sq);
        float scale = __fdividef(sqrtf(sq), 1.0f + sq);
        #pragma unroll
        for (int j = 0; j < DOV; j++) vr[j] = sac[j] * scale;
    }

    // ---------------- iterations 1 and 2
    #pragma unroll 1
    for (int t = 1; t < 3; t++) {
        #pragma unroll
        for (int j = 0; j < DOV; j++) sac[j] = 0.0f;

        const uint4* p0 = reinterpret_cast<const uint4*>(ub + (size_t)ii * DOV);
        uint4 ua = p0[0], ux = p0[1];

        for (int ti = 0; ti < NT; ti++) {
            const int tn = (ti + 1 < NT) ? (ti + 1) : (NT - 1);
            const uint4* pn = reinterpret_cast<const uint4*>(
                ub + (size_t)(tn * 32 + ii) * DOV);
            uint4 na = pn[0], nb = pn[1];

            float u[DOV];
            unpack16(ua, ux, u);

            float a = u[0] * vr[0];
            #pragma unroll
            for (int j = 1; j < DOV; j++) a = fmaf(u[j], vr[j], a);
            // |logit| bounded (~35): exp safe in fp32 without max-subtract
            float e = __expf(a);
            const int pb = ti & 1;
            e_s[pb][c][ii] = e;
            __syncthreads();
            float Z = e_s[pb][0][ii];
            #pragma unroll
            for (int cc = 1; cc < CCL; cc++) Z += e_s[pb][cc][ii];
            float w = __fdividef(e, Z);

            #pragma unroll
            for (int j = 0; j < DOV; j++) sac[j] = fmaf(w, u[j], sac[j]);

            ua = na; ux = nb;
        }

        #pragma unroll
        for (int off = 16; off > 0; off >>= 1)
            #pragma unroll
            for (int j = 0; j < DOV; j++)
                sac[j] += __shfl_xor_sync(0xffffffffu, sac[j], off);

        float sq = 0.0f;
        #pragma unroll
        for (int j = 0; j < DOV; j++) sq = fmaf(sac[j], sac[j], sq);
        float scale = __fdividef(sqrtf(sq), 1.0f + sq);

        if (t == 2) {
            if (ii == 0) {
                float4* op = reinterpret_cast<float4*>(
                    out + ((size_t)b * CCL + c) * DOV);
                op[0] = make_float4(sac[0]*scale,  sac[1]*scale,  sac[2]*scale,  sac[3]*scale);
                op[1] = make_float4(sac[4]*scale,  sac[5]*scale,  sac[6]*scale,  sac[7]*scale);
                op[2] = make_float4(sac[8]*scale,  sac[9]*scale,  sac[10]*scale, sac[11]*scale);
                op[3] = make_float4(sac[12]*scale, sac[13]*scale, sac[14]*scale, sac[15]*scale);
            }
        } else {
            #pragma unroll
            for (int j = 0; j < DOV; j++) vr[j] += sac[j] * scale;
        }
    }
}

// ---------------------------------------------------------------------------
extern "C" void kernel_launch(void* const* d_in, const int* in_sizes, int n_in,
                              void* d_out, int out_size)
{
    const float* x = (const float*)d_in[0];
    const float* W = (const float*)d_in[1];
    if (in_sizes[0] == CCL * ICAP * DOV * DIV) {  // defensively identify by size
        const float* t = x; x = W; W = t;
    }
    float* out = (float*)d_out;

    cudaFuncSetAttribute(uhat_kernel,
                         cudaFuncAttributeMaxDynamicSharedMemorySize, UH_SMEM);

    uhat_kernel<<<ICAP / ICH, 256, UH_SMEM>>>(x, W);
    route_kernel<<<BSZ, 320>>>(out);
}